// round 4
// baseline (speedup 1.0000x reference)
#include <cuda_runtime.h>

#define Bn 32
#define Nn 1024
#define Cn 768
#define C4 192        // Cn / 4
#define ZCHUNK 32
#define ROWS_PER_Z 32 // Nn / ZCHUNK
#define POOL_BLOCKS (Bn * ZCHUNK)   // 1024
#define ORBITS 272
#define MERGE_BLOCKS (Bn * ORBITS)  // 8704

// Scratch (no allocation allowed in kernel_launch)
__device__ float g_pdot[Bn * ZCHUNK * 4];  // per-(b,z) partial dot with W
__device__ float g_alpha[Bn * 4];          // per-batch merge coefficients
__device__ int   g_cnt[Bn];                // pool completion tickets
__device__ int   g_flag[Bn];               // alpha-ready flags

__global__ void reset_kernel() {
    int t = threadIdx.x;
    if (t < Bn) { g_cnt[t] = 0; g_flag[t] = 0; }
}

__global__ void __launch_bounds__(192) fused_kernel(
    const float* __restrict__ x,
    const float* __restrict__ W,
    const float* __restrict__ bias,
    float* __restrict__ out) {
    int tid = threadIdx.x;  // 0..191

    if (blockIdx.x < POOL_BLOCKS) {
        // ───────────────────────── pool + W-dot task ─────────────────────────
        int b = blockIdx.x >> 5;   // batch
        int z = blockIdx.x & 31;   // row chunk
        const float4* p = (const float4*)(x + ((size_t)b * Nn + (size_t)z * ROWS_PER_Z) * Cn) + tid;

        float4 a0 = {0,0,0,0}, a1 = {0,0,0,0}, a2 = {0,0,0,0}, a3 = {0,0,0,0};
#pragma unroll
        for (int n = 0; n < ROWS_PER_Z; n += 8) {
            float4 v[8];
#pragma unroll
            for (int u = 0; u < 8; u++)
                v[u] = p[(size_t)(n + u) * C4];
            a0.x += v[0].x + v[4].x; a0.y += v[0].y + v[4].y;
            a0.z += v[0].z + v[4].z; a0.w += v[0].w + v[4].w;
            a1.x += v[1].x + v[5].x; a1.y += v[1].y + v[5].y;
            a1.z += v[1].z + v[5].z; a1.w += v[1].w + v[5].w;
            a2.x += v[2].x + v[6].x; a2.y += v[2].y + v[6].y;
            a2.z += v[2].z + v[6].z; a2.w += v[2].w + v[6].w;
            a3.x += v[3].x + v[7].x; a3.y += v[3].y + v[7].y;
            a3.z += v[3].z + v[7].z; a3.w += v[3].w + v[7].w;
        }
        float4 s;
        s.x = (a0.x + a1.x) + (a2.x + a3.x);
        s.y = (a0.y + a1.y) + (a2.y + a3.y);
        s.z = (a0.z + a1.z) + (a2.z + a3.z);
        s.w = (a0.w + a1.w) + (a2.w + a3.w);

        // per-thread dot with W rows (thread owns channels 4*tid..4*tid+3)
        float d[4];
#pragma unroll
        for (int k = 0; k < 4; k++) {
            float4 w4 = ((const float4*)W)[k * C4 + tid];
            d[k] = s.x * w4.x + s.y * w4.y + s.z * w4.z + s.w * w4.w;
        }
        // block reduce 4 values over 6 warps
        __shared__ float sdot[6][4];
        int lane = tid & 31, wid = tid >> 5;
#pragma unroll
        for (int k = 0; k < 4; k++) {
#pragma unroll
            for (int off = 16; off > 0; off >>= 1)
                d[k] += __shfl_down_sync(0xffffffffu, d[k], off);
            if (lane == 0) sdot[wid][k] = d[k];
        }
        __syncthreads();
        if (tid < 32) {
            int k = tid & 3, w = tid >> 2;  // w = 0..7 (pad >5 with 0)
            float v = (w < 6) ? sdot[w][k] : 0.f;
            v += __shfl_down_sync(0xffffffffu, v, 16);
            v += __shfl_down_sync(0xffffffffu, v, 8);
            v += __shfl_down_sync(0xffffffffu, v, 4);
            if (tid < 4)
                __stcg(&g_pdot[((size_t)b * ZCHUNK + z) * 4 + k], v);
        }

        // completion ticket; last block finalizes alpha[b] and releases flag
        __shared__ int ticket;
        __threadfence();
        __syncthreads();
        if (tid == 0) ticket = atomicAdd(&g_cnt[b], 1);
        __syncthreads();
        if (ticket == ZCHUNK - 1) {
            if (tid < 4) {
                float sum = 0.f;
#pragma unroll
                for (int zz = 0; zz < ZCHUNK; zz++)
                    sum += __ldcg(&g_pdot[((size_t)b * ZCHUNK + zz) * 4 + tid]);
                __stcg(&g_alpha[b * 4 + tid], sum * (1.0f / 1024.0f) + bias[tid]);
            }
            __threadfence();
            __syncthreads();
            if (tid == 0) atomicExch(&g_flag[b], 1);
        }
    } else {
        // ───────────────────────── orbit merge task ─────────────────────────
        int mb = blockIdx.x - POOL_BLOCKS;
        int b = mb / ORBITS;
        int o = mb % ORBITS;
        int i = 0, cnt = 32;
        while (o >= cnt) { o -= cnt; i++; cnt -= 2; }
        int j = i + o;

        int l   = (i << 5) | j;
        int tl  = (j << 5) | i;
        int rl  = 1023 - l;
        int rtl = 1023 - tl;

        // wait for alpha[b]
        __shared__ int ready;
        if (tid == 0) {
            while (atomicAdd(&g_flag[b], 0) == 0)
                __nanosleep(64);
            ready = 1;
        }
        __syncthreads();
        (void)ready;
        __threadfence();

        float c0 = __ldcg(&g_alpha[b * 4 + 0]);
        float c1 = __ldcg(&g_alpha[b * 4 + 1]);
        float c2 = __ldcg(&g_alpha[b * 4 + 2]);
        float c3 = __ldcg(&g_alpha[b * 4 + 3]);

        const float4* xb = (const float4*)(x + (size_t)b * Nn * Cn);
        float4*       ob = (float4*)(out + (size_t)b * Nn * Cn);

        float4 v0 = xb[(size_t)l   * C4 + tid];
        float4 v1 = xb[(size_t)tl  * C4 + tid];
        float4 v2 = xb[(size_t)rl  * C4 + tid];
        float4 v3 = xb[(size_t)rtl * C4 + tid];

        float4 w;
        // out[l] = c0 v0 + c1 v1 + c2 v2 + c3 v3
        w.x = fmaf(c0, v0.x, fmaf(c1, v1.x, fmaf(c2, v2.x, c3 * v3.x)));
        w.y = fmaf(c0, v0.y, fmaf(c1, v1.y, fmaf(c2, v2.y, c3 * v3.y)));
        w.z = fmaf(c0, v0.z, fmaf(c1, v1.z, fmaf(c2, v2.z, c3 * v3.z)));
        w.w = fmaf(c0, v0.w, fmaf(c1, v1.w, fmaf(c2, v2.w, c3 * v3.w)));
        __stcs(&ob[(size_t)l * C4 + tid], w);

        // out[tl] = c0 v1 + c1 v0 + c2 v3 + c3 v2
        w.x = fmaf(c0, v1.x, fmaf(c1, v0.x, fmaf(c2, v3.x, c3 * v2.x)));
        w.y = fmaf(c0, v1.y, fmaf(c1, v0.y, fmaf(c2, v3.y, c3 * v2.y)));
        w.z = fmaf(c0, v1.z, fmaf(c1, v0.z, fmaf(c2, v3.z, c3 * v2.z)));
        w.w = fmaf(c0, v1.w, fmaf(c1, v0.w, fmaf(c2, v3.w, c3 * v2.w)));
        __stcs(&ob[(size_t)tl * C4 + tid], w);

        // out[rl] = c0 v2 + c1 v3 + c2 v0 + c3 v1
        w.x = fmaf(c0, v2.x, fmaf(c1, v3.x, fmaf(c2, v0.x, c3 * v1.x)));
        w.y = fmaf(c0, v2.y, fmaf(c1, v3.y, fmaf(c2, v0.y, c3 * v1.y)));
        w.z = fmaf(c0, v2.z, fmaf(c1, v3.z, fmaf(c2, v0.z, c3 * v1.z)));
        w.w = fmaf(c0, v2.w, fmaf(c1, v3.w, fmaf(c2, v0.w, c3 * v1.w)));
        __stcs(&ob[(size_t)rl * C4 + tid], w);

        // out[rtl] = c0 v3 + c1 v2 + c2 v1 + c3 v0
        w.x = fmaf(c0, v3.x, fmaf(c1, v2.x, fmaf(c2, v1.x, c3 * v0.x)));
        w.y = fmaf(c0, v3.y, fmaf(c1, v2.y, fmaf(c2, v1.y, c3 * v0.y)));
        w.z = fmaf(c0, v3.z, fmaf(c1, v2.z, fmaf(c2, v1.z, c3 * v0.z)));
        w.w = fmaf(c0, v3.w, fmaf(c1, v2.w, fmaf(c2, v1.w, c3 * v0.w)));
        __stcs(&ob[(size_t)rtl * C4 + tid], w);
    }
}

extern "C" void kernel_launch(void* const* d_in, const int* in_sizes, int n_in,
                              void* d_out, int out_size) {
    const float* x    = (const float*)d_in[0];  // (32,1024,768)
    const float* W    = (const float*)d_in[1];  // (4,768)
    const float* bias = (const float*)d_in[2];  // (4,)
    float* out = (float*)d_out;

    reset_kernel<<<1, 64>>>();
    fused_kernel<<<POOL_BLOCKS + MERGE_BLOCKS, 192>>>(x, W, bias, out);
}